// round 7
// baseline (speedup 1.0000x reference)
#include <cuda_runtime.h>
#include <cstdint>

typedef unsigned int u32;
typedef unsigned long long u64;

// ---------------- BabyBear constants (compile time) ----------------
constexpr u32 PRIME = 2013265921u;
constexpr u32 calc_pinv() {                 // -P^{-1} mod 2^32 (for Montgomery twiddle gen)
    u32 inv = 1u;
    for (int i = 0; i < 5; ++i) inv *= (2u - PRIME * inv);
    return (u32)(0u - inv);
}
constexpr u32 PINV = calc_pinv();
constexpr u64 R1v  = (((u64)1) << 32) % PRIME;           // R mod P
constexpr u32 R2C  = (u32)((R1v * R1v) % PRIME);         // R^2 mod P
constexpr u64 cpow(u64 b, u64 e) {
    u64 r = 1; b %= PRIME;
    while (e) { if (e & 1) r = r * b % PRIME; b = b * b % PRIME; e >>= 1; }
    return r;
}
constexpr u32 OMEGA = (u32)cpow(31, 480);                // GEN^((P-1)/2^22)
constexpr u32 WRAPC = (u32)((((u64)1) << 32) % PRIME);   // 2^32 mod P = 268435454
constexpr u32 PCORR = PRIME - WRAPC;                     // 1744830467
constexpr u32 SSTRIDE = 2180u;                           // per-team shared stride (words)

// ---------------- device scratch ----------------
__device__ u32 g_mid[1u << 25];     // 128MB intermediate, standard-form residues
__device__ u32 g_twA_M[1024];       // Montgomery: omega_2048^q * R
__device__ u32 g_twA_S[1024];       // standard:  omega_2048^q
__device__ u32 g_twB_S[2048];       // standard:  omega^r

// ---------------- exact modular helpers (twiddle generation only) ----------------
__device__ __forceinline__ u32 mmul(u32 a, u32 b) {      // a*b*R^{-1} mod P (exact)
    u64 t = (u64)a * b;
    u32 m = (u32)t * PINV;
    u32 r = (u32)((t + (u64)m * PRIME) >> 32);
    return r >= PRIME ? r - PRIME : r;
}
__device__ __forceinline__ u32 subm(u32 a, u32 b) { return a >= b ? a - b : a + (PRIME - b); }

// ---------------- int32-wrap emulation (matches JAX x32 reference semantics) ----
// value of ((int32)(a*b)) mod P, result non-negative — replicates `a * b % P` in int32 JAX
__device__ __forceinline__ u32 wmul(u32 a, u32 b) {
    u32 m = a * b;                       // low 32 bits (wraps like the reference)
    u32 r = m;
    if (r >= 2u * PRIME) r -= 2u * PRIME;
    if (r >= PRIME)      r -= PRIME;     // r = m mod P
    if (m & 0x80000000u) { r += PCORR; if (r >= PRIME) r -= PRIME; }  // signed-wrap fixup
    return r;
}
// value of ((int32)(a+b)) mod P for a,b in [0,P)
__device__ __forceinline__ u32 wadd(u32 a, u32 b) {
    u32 t = a + b;                       // < 2P, no u32 wrap
    u32 r = (t >= PRIME) ? t - PRIME : t;
    if (t & 0x80000000u) { r += PCORR; if (r >= PRIME) r -= PRIME; }  // int32 overflow fixup
    return r;
}
__device__ __forceinline__ u32 swz(u32 j) { return j + (j >> 4); }

// dtype-adaptive load (buffers may be int32 or float32 encodings of the residues)
__device__ __forceinline__ u32 ldval(const void* p, u32 i, bool fm) {
    if (fm) return (u32)__ldg((const float*)p + i);
    return (u32)__ldg((const int*)p + i);
}
__device__ __forceinline__ int pick(const void* const* cand, int n, u32 want, bool& fm) {
    u32 fwant = __float_as_uint((float)want);
    for (int i = 0; i < n; ++i) {
        u32 raw = ((const u32*)cand[i])[1];
        if (raw == want)  { fm = false; return i; }
        if (raw == fwant) { fm = true;  return i; }
    }
    fm = false; return 0;
}

// wrapped butterfly: exact replication of reference `v=x*w%p; (u+v)%p; (u-v)%p`
#define BFLYW(A, B, W) { u32 _vw = wmul((B), (W)); u32 _a = (A); (B) = subm(_a, _vw); (A) = wadd(_a, _vw); }

// ---------------- setup: twiddle tables from the forward table ----------------
__global__ void k_setup(const void* tw0, const void* tw1) {
    const void* cand[2] = { tw0, tw1 };
    bool fm;
    const void* tw = cand[pick(cand, 2, OMEGA, fm)];   // forward twiddles: tw[1] == omega
    u32 q = blockIdx.x * blockDim.x + threadIdx.x;     // [0,2048)
    if (q < 2048) {
        g_twB_S[q] = ldval(tw, q, fm);                 // omega^q exact
        if (q < 1024) {
            u32 v = ldval(tw, q << 11, fm);            // omega_2048^q = omega^(2048q) exact
            g_twA_S[q] = v;
            g_twA_M[q] = mmul(v, R2C);                 // Montgomery form
        }
    }
}

// ---------------- 2048-point stage block (reference stages, wrapped ops) ------
// P2=false: reference stages 1..11 (twiddle omega_2048^q, exact from g_twA_S).
// P2=true : reference stages 12..22 for fixed k1 (twiddle omega^{(k1+2048q)*2^{11-s}}
//           = mmul(g_twA_M[q<<(11-s)], base_s),  base_s = omega^{k1<<(11-s)} exact).
template<bool P2>
__device__ __forceinline__ void ntt2048_team(u32* col, u32 u, u32 k1) {
    u32 x[16];
    u32 r7 = __brev(u) >> 25;                          // rev7(u)

    // ---- phase A (stages s=1..4): working j = 16u+e ; source = rev4(e)<<7 | rev7(u)
    #pragma unroll
    for (int e = 0; e < 16; ++e) {
        u32 rev4e = ((e & 1) << 3) | ((e & 2) << 1) | ((e & 4) >> 1) | ((e & 8) >> 3);
        x[e] = col[swz((rev4e << 7) | r7)];
    }
    // stage 1
    if constexpr (P2) {
        u32 E = k1 << 10;
        u32 base = mmul(g_twA_M[E >> 11], g_twB_S[E & 2047u]);   // omega^{k1<<10} exact
        #pragma unroll
        for (int e = 0; e < 16; e += 2) BFLYW(x[e], x[e + 1], base);
    } else {
        #pragma unroll
        for (int e = 0; e < 16; e += 2) {               // w = 1 (wrap-free: v'=v exactly)
            u32 a = x[e], v = x[e + 1];
            x[e] = wadd(a, v); x[e + 1] = subm(a, v);
        }
    }
    #pragma unroll
    for (int s = 2; s <= 4; ++s) {
        const int h = 1 << (s - 1);
        u32 base = 0;
        if constexpr (P2) {
            u32 E = k1 << (11 - s);
            base = mmul(g_twA_M[E >> 11], g_twB_S[E & 2047u]);
        }
        #pragma unroll
        for (int bq = 0; bq < 16; bq += 2 * h)
            #pragma unroll
            for (int k = 0; k < h; ++k) {
                u32 idx = (u32)k << (11 - s);
                u32 w = P2 ? mmul(g_twA_M[idx], base) : g_twA_S[idx];
                BFLYW(x[bq + k], x[bq + k + h], w);
            }
    }
    __syncthreads();
    #pragma unroll
    for (int e = 0; e < 16; ++e) col[swz(16u * u + e)] = x[e];
    __syncthreads();

    // ---- phase B (stages s=5..8): j = (u&15) | ((u>>4)<<8) | (e<<4)
    u32 baseB = (u & 15u) | ((u >> 4) << 8);
    u32 plow  = u & 15u;
    #pragma unroll
    for (int e = 0; e < 16; ++e) x[e] = col[swz(baseB | ((u32)e << 4))];
    #pragma unroll
    for (int s = 5; s <= 8; ++s) {
        const int h = 1 << (s - 5);
        u32 base = 0;
        if constexpr (P2) {
            u32 E = k1 << (11 - s);
            base = mmul(g_twA_M[E >> 11], g_twB_S[E & 2047u]);
        }
        #pragma unroll
        for (int bq = 0; bq < 16; bq += 2 * h)
            #pragma unroll
            for (int k = 0; k < h; ++k) {
                u32 q = plow | ((u32)k << 4);
                u32 idx = q << (11 - s);
                u32 w = P2 ? mmul(g_twA_M[idx], base) : g_twA_S[idx];
                BFLYW(x[bq + k], x[bq + k + h], w);
            }
    }
    #pragma unroll
    for (int e = 0; e < 16; ++e) col[swz(baseB | ((u32)e << 4))] = x[e];
    __syncthreads();

    // ---- phase C (stages s=9..11): j = u | (g<<7) | (e<<8)
    #pragma unroll
    for (int g = 0; g < 2; ++g)
        #pragma unroll
        for (int e = 0; e < 8; ++e) x[g * 8 + e] = col[swz(u | ((u32)g << 7) | ((u32)e << 8))];
    #pragma unroll
    for (int s = 9; s <= 11; ++s) {
        const int h = 1 << (s - 9);
        u32 base = 0;
        if constexpr (P2) {
            u32 E = k1 << (11 - s);
            base = mmul(g_twA_M[E >> 11], g_twB_S[E & 2047u]);
        }
        #pragma unroll
        for (int g = 0; g < 2; ++g) {
            u32 pg = u | ((u32)g << 7);
            #pragma unroll
            for (int bq = 0; bq < 8; bq += 2 * h)
                #pragma unroll
                for (int k = 0; k < h; ++k) {
                    u32 idx = (pg | ((u32)k << 8)) << (11 - s);
                    u32 w = P2 ? mmul(g_twA_M[idx], base) : g_twA_S[idx];
                    BFLYW(x[g * 8 + bq + k], x[g * 8 + bq + k + h], w);
                }
        }
    }
    #pragma unroll
    for (int g = 0; g < 2; ++g)
        #pragma unroll
        for (int e = 0; e < 8; ++e) col[swz(u | ((u32)g << 7) | ((u32)e << 8))] = x[g * 8 + e];
    __syncthreads();
}

// ---------------- pass 1: reference stages 1..11 per column -> g_mid ----------
__global__ void __launch_bounds__(1024, 1)
k_pass1(const void* __restrict__ in,
        const void* c0, const void* c1, const void* c2,
        const void* tw0, const void* tw1) {
    extern __shared__ u32 sh[];
    const void* ccand[3] = { c0, c1, c2 };
    bool fm_cos, fm_in;
    const void* coset = ccand[pick(ccand, 3, 3u, fm_cos)];   // coset_powers[1] == 3
    {   const void* tcand[2] = { tw0, tw1 };
        pick(tcand, 2, OMEGA, fm_in);                         // input shares canonical dtype
    }

    const u32 t  = threadIdx.x;
    const u32 b  = blockIdx.y;
    const u32 cb = blockIdx.x * 8u;          // 8 columns per CTA
    const u32 r  = t >> 3, cc = t & 7u;
    const u32 base_in = b << 22;

    #pragma unroll
    for (int e = 0; e < 16; ++e) {
        u32 j1   = r + 128u * (u32)e;
        u32 gidx = j1 * 2048u + cb + cc;
        u32 v = ldval(in, base_in + gidx, fm_in);
        v = wmul(v, ldval(coset, gidx, fm_cos));   // wrapped `input * coset % P`
        sh[cc * SSTRIDE + swz(j1)] = v;
    }
    __syncthreads();

    ntt2048_team<false>(sh + (t >> 7) * SSTRIDE, t & 127u, 0u);

    const u32 j2 = cb + cc;
    #pragma unroll
    for (int e = 0; e < 16; ++e) {
        u32 k1 = r + 128u * (u32)e;
        g_mid[base_in | (k1 * 2048u + j2)] = sh[cc * SSTRIDE + swz(k1)];
    }
}

// ---------------- pass 2: reference stages 12..22 per k1 -> d_out (float32) ---
__global__ void __launch_bounds__(1024, 1)
k_pass2(float* __restrict__ out) {
    extern __shared__ u32 sh[];
    const u32 t  = threadIdx.x;
    const u32 b  = blockIdx.y;
    const u32 rb = blockIdx.x * 8u;          // 8 k1-rows per CTA
    const u32 mbase = (b << 22) | (rb * 2048u);

    #pragma unroll
    for (int e = 0; e < 16; ++e) {
        u32 f = t + 1024u * (u32)e;          // coalesced read of 8 rows
        u32 v = g_mid[mbase + f];
        sh[(f >> 11) * SSTRIDE + swz(f & 2047u)] = v;   // natural j2 order
    }
    __syncthreads();

    ntt2048_team<true>(sh + (t >> 7) * SSTRIDE, t & 127u, rb + (t >> 7));

    const u32 r = t >> 3, cc = t & 7u;
    const u32 k1 = rb + cc;
    const u32 obase = b << 22;
    #pragma unroll
    for (int e = 0; e < 16; ++e) {
        u32 k2   = r + 128u * (u32)e;
        u32 v    = sh[cc * SSTRIDE + swz(k2)];
        out[obase + k1 + (k2 << 11)] = (float)v;   // output buffer is float32
    }
}

// ---------------- launch ----------------
extern "C" void kernel_launch(void* const* d_in, const int* in_sizes, int n_in,
                              void* d_out, int out_size) {
    const void* inp = nullptr;
    const void* tw[2] = { nullptr, nullptr };
    const void* cs[3] = { nullptr, nullptr, nullptr };
    int ntw = 0, ncs = 0;
    for (int i = 0; i < n_in; ++i) {
        long long sz = in_sizes[i];
        if (sz == (1LL << 25)) inp = d_in[i];
        else if (sz == (1LL << 21) && ntw < 2) tw[ntw++] = d_in[i];
        else if (sz == (1LL << 22) && ncs < 3) cs[ncs++] = d_in[i];
    }
    if (!inp)    inp   = d_in[0];
    if (ntw < 2) { tw[0] = d_in[1]; tw[1] = d_in[2]; }
    if (ncs < 3) { cs[0] = d_in[3]; cs[1] = d_in[4]; cs[2] = d_in[5]; }

    const int smem = 8 * SSTRIDE * (int)sizeof(u32);   // 69760 B
    cudaFuncSetAttribute(k_pass1, cudaFuncAttributeMaxDynamicSharedMemorySize, smem);
    cudaFuncSetAttribute(k_pass2, cudaFuncAttributeMaxDynamicSharedMemorySize, smem);

    k_setup<<<8, 256>>>(tw[0], tw[1]);
    dim3 grid(256, 8);
    k_pass1<<<grid, 1024, smem>>>(inp, cs[0], cs[1], cs[2], tw[0], tw[1]);
    k_pass2<<<grid, 1024, smem>>>((float*)d_out);
}

// round 8
// speedup vs baseline: 1.4926x; 1.4926x over previous
#include <cuda_runtime.h>
#include <cstdint>

typedef unsigned int u32;
typedef unsigned long long u64;

// ---------------- BabyBear constants (compile time) ----------------
constexpr u32 PRIME = 2013265921u;
constexpr u32 calc_pinv() {                 // -P^{-1} mod 2^32 (Montgomery, twiddle gen only)
    u32 inv = 1u;
    for (int i = 0; i < 5; ++i) inv *= (2u - PRIME * inv);
    return (u32)(0u - inv);
}
constexpr u32 PINV = calc_pinv();
constexpr u64 R1v  = (((u64)1) << 32) % PRIME;
constexpr u32 R2C  = (u32)((R1v * R1v) % PRIME);
constexpr u64 cpow(u64 b, u64 e) {
    u64 r = 1; b %= PRIME;
    while (e) { if (e & 1) r = r * b % PRIME; b = b * b % PRIME; e >>= 1; }
    return r;
}
constexpr u32 OMEGA = (u32)cpow(31, 480);                // GEN^((P-1)/2^22)
constexpr u32 WRAPC = (u32)((((u64)1) << 32) % PRIME);   // 2^32 mod P
constexpr u32 PCORR = PRIME - WRAPC;                     // 1744830467
constexpr u32 SSTRIDE = 2180u;                           // per-team shared stride (words)

// ---------------- device scratch ----------------
__device__ u32 g_mid[1u << 25];     // 128MB intermediate, standard-form residues
__device__ u32 g_twA_S[1024];       // standard:  omega_2048^q
__device__ u32 g_twA_M[1024];       // Montgomery: omega_2048^q * R
__device__ u32 g_twB_S[2048];       // standard:  omega^r
__device__ u32 g_seqS[29 * 128];    // slot-sequenced per-thread twiddles (standard)
__device__ u32 g_seqM[29 * 128];    // same, Montgomery form (for pass-2 twisting)

// ---------------- exact modular helpers (twiddle generation only) --------------
__device__ __forceinline__ u32 mmul(u32 a, u32 b) {      // a*b*R^{-1} mod P (exact)
    u64 t = (u64)a * b;
    u32 m = (u32)t * PINV;
    u32 r = (u32)((t + (u64)m * PRIME) >> 32);
    return r >= PRIME ? r - PRIME : r;
}
__device__ __forceinline__ u32 subm(u32 a, u32 b) { return a >= b ? a - b : a + (PRIME - b); }

// ---------------- int32-wrap emulation (JAX x32 reference semantics) -----------
__device__ __forceinline__ u32 wmul(u32 a, u32 b) {      // ((int32)(a*b)) mod P
    u32 m = a * b;                       // low 32 bits, wraps like the reference
    u32 r = m;
    if (r >= 2u * PRIME) r -= 2u * PRIME;
    if (r >= PRIME)      r -= PRIME;
    if (m & 0x80000000u) { r += PCORR; if (r >= PRIME) r -= PRIME; }
    return r;
}
__device__ __forceinline__ u32 wadd(u32 a, u32 b) {      // ((int32)(a+b)) mod P, a,b in [0,P)
    u32 t = a + b;
    u32 r = (t >= PRIME) ? t - PRIME : t;
    if (t & 0x80000000u) { r += PCORR; if (r >= PRIME) r -= PRIME; }
    return r;
}
__device__ __forceinline__ u32 swz(u32 j) { return j + (j >> 4); }

__device__ __forceinline__ u32 ldval(const void* p, u32 i, bool fm) {
    if (fm) return (u32)__ldg((const float*)p + i);
    return (u32)__ldg((const int*)p + i);
}
__device__ __forceinline__ int pick(const void* const* cand, int n, u32 want, bool& fm) {
    u32 fwant = __float_as_uint((float)want);
    for (int i = 0; i < n; ++i) {
        u32 raw = ((const u32*)cand[i])[1];
        if (raw == want)  { fm = false; return i; }
        if (raw == fwant) { fm = true;  return i; }
    }
    fm = false; return 0;
}

#define BFLYW(A, B, W) { u32 _vw = wmul((B), (W)); u32 _a = (A); (B) = subm(_a, _vw); (A) = wadd(_a, _vw); }
#define TBAR(id) asm volatile("bar.sync %0, 128;" :: "r"(id) : "memory")

// pass-2 per-stage base twiddle: omega^{k1 * 2^{11-s}} (exact standard form)
__device__ __forceinline__ u32 p2base(u32 k1, int s) {
    u32 E = k1 << (11 - s);              // < 2^21
    return mmul(__ldg(&g_twA_M[E >> 11]), __ldg(&g_twB_S[E & 2047u]));
}

// slot -> omega_2048 exponent for thread position u (matches consumption order below)
__device__ u32 slot_idx(u32 slot, u32 u) {
    u32 plow = u & 15u;
    if (slot == 0)  return plow << 6;                                   // s5
    if (slot < 3)   return (plow | ((slot - 1) << 4)) << 5;             // s6, k=slot-1
    if (slot < 7)   return (plow | ((slot - 3) << 4)) << 4;             // s7
    if (slot < 15)  return (plow | ((slot - 7) << 4)) << 3;             // s8
    if (slot < 17)  return (u | ((slot - 15) << 7)) << 2;               // s9, g=slot-15
    if (slot < 21)  { u32 g = (slot - 17) >> 1, k = (slot - 17) & 1;
                      return ((u | (g << 7)) | (k << 8)) << 1; }        // s10
    { u32 g = (slot - 21) >> 2, k = (slot - 21) & 3;
      return (u | (g << 7)) | (k << 8); }                               // s11
}

// ---------------- setup: all twiddle tables from the forward input table -------
__global__ void k_setup(const void* tw0, const void* tw1) {
    const void* cand[2] = { tw0, tw1 };
    bool fm;
    const void* tw = cand[pick(cand, 2, OMEGA, fm)];   // forward twiddles: tw[1] == omega
    u32 i = blockIdx.x * blockDim.x + threadIdx.x;
    if (i < 2048) {
        g_twB_S[i] = ldval(tw, i, fm);
    } else if (i < 3072) {
        u32 q = i - 2048;
        u32 v = ldval(tw, q << 11, fm);                // omega_2048^q exact
        g_twA_S[q] = v;
        g_twA_M[q] = mmul(v, R2C);
    } else if (i < 3072 + 29 * 128) {
        u32 s = i - 3072;
        u32 idx = slot_idx(s >> 7, s & 127u);
        u32 v = ldval(tw, idx << 11, fm);
        g_seqS[s] = v;
        g_seqM[s] = mmul(v, R2C);
    }
}

// ---------------- 2048-point stage block (reference stages, wrapped ops) -------
// P2=false: reference stages 1..11. P2=true: stages 12..22 for fixed k1 (twisted).
// Caller must __syncthreads() before (data ready) and after (before cross-team reads).
template<bool P2>
__device__ __forceinline__ void ntt2048_team(u32* col, u32 u, u32 k1, u32 bar) {
    u32 x[16];
    u32 r7 = __brev(u) >> 25;                          // rev7(u)

    // ---- phase A (stages 1..4): j = 16u+e ; bitrev source = rev4(e)<<7 | rev7(u)
    #pragma unroll
    for (int e = 0; e < 16; ++e) {
        u32 rev4e = ((e & 1) << 3) | ((e & 2) << 1) | ((e & 4) >> 1) | ((e & 8) >> 3);
        x[e] = col[swz((rev4e << 7) | r7)];
    }
    if constexpr (P2) {
        u32 w = p2base(k1, 1);
        #pragma unroll
        for (int e = 0; e < 16; e += 2) BFLYW(x[e], x[e + 1], w);
    } else {
        #pragma unroll
        for (int e = 0; e < 16; e += 2) {               // w = 1, wrap-exact shortcut
            u32 a = x[e], v = x[e + 1];
            x[e] = wadd(a, v); x[e + 1] = subm(a, v);
        }
    }
    #pragma unroll
    for (int s = 2; s <= 4; ++s) {
        const int h = 1 << (s - 1);
        u32 base = 0;
        if constexpr (P2) base = p2base(k1, s);
        #pragma unroll
        for (int k = 0; k < h; ++k) {                   // k outer: one w per distinct twiddle
            u32 w;
            if constexpr (P2) w = mmul(__ldg(&g_twA_M[(u32)k << (11 - s)]), base);
            else              w = __ldg(&g_twA_S[(u32)k << (11 - s)]);
            #pragma unroll
            for (int bq = 0; bq < 16; bq += 2 * h)
                BFLYW(x[bq + k], x[bq + k + h], w);
        }
    }
    TBAR(bar);
    #pragma unroll
    for (int e = 0; e < 16; ++e) col[swz(16u * u + e)] = x[e];
    TBAR(bar);

    // ---- phase B (stages 5..8): j = (u&15) | ((u>>4)<<8) | (e<<4)
    u32 baseB = (u & 15u) | ((u >> 4) << 8);
    u32 wB[15];
    #pragma unroll
    for (int i = 0; i < 15; ++i)                        // coalesced slot loads
        wB[i] = P2 ? __ldg(&g_seqM[i * 128 + u]) : __ldg(&g_seqS[i * 128 + u]);
    #pragma unroll
    for (int e = 0; e < 16; ++e) x[e] = col[swz(baseB | ((u32)e << 4))];
    {   // stage 5
        u32 w = wB[0];
        if constexpr (P2) w = mmul(w, p2base(k1, 5));
        #pragma unroll
        for (int bq = 0; bq < 16; bq += 2) BFLYW(x[bq], x[bq + 1], w);
    }
    {   // stage 6
        u32 base = 0; if constexpr (P2) base = p2base(k1, 6);
        #pragma unroll
        for (int k = 0; k < 2; ++k) {
            u32 w = wB[1 + k]; if constexpr (P2) w = mmul(w, base);
            #pragma unroll
            for (int bq = 0; bq < 16; bq += 4) BFLYW(x[bq + k], x[bq + k + 2], w);
        }
    }
    {   // stage 7
        u32 base = 0; if constexpr (P2) base = p2base(k1, 7);
        #pragma unroll
        for (int k = 0; k < 4; ++k) {
            u32 w = wB[3 + k]; if constexpr (P2) w = mmul(w, base);
            #pragma unroll
            for (int bq = 0; bq < 16; bq += 8) BFLYW(x[bq + k], x[bq + k + 4], w);
        }
    }
    {   // stage 8
        u32 base = 0; if constexpr (P2) base = p2base(k1, 8);
        #pragma unroll
        for (int k = 0; k < 8; ++k) {
            u32 w = wB[7 + k]; if constexpr (P2) w = mmul(w, base);
            BFLYW(x[k], x[k + 8], w);
        }
    }
    #pragma unroll
    for (int e = 0; e < 16; ++e) col[swz(baseB | ((u32)e << 4))] = x[e];
    TBAR(bar);

    // ---- phase C (stages 9..11): j = u | (g<<7) | (e<<8)
    u32 wC[14];
    #pragma unroll
    for (int i = 0; i < 14; ++i)
        wC[i] = P2 ? __ldg(&g_seqM[(15 + i) * 128 + u]) : __ldg(&g_seqS[(15 + i) * 128 + u]);
    #pragma unroll
    for (int g = 0; g < 2; ++g)
        #pragma unroll
        for (int e = 0; e < 8; ++e) x[g * 8 + e] = col[swz(u | ((u32)g << 7) | ((u32)e << 8))];
    {   // stage 9
        u32 base = 0; if constexpr (P2) base = p2base(k1, 9);
        #pragma unroll
        for (int g = 0; g < 2; ++g) {
            u32 w = wC[g]; if constexpr (P2) w = mmul(w, base);
            #pragma unroll
            for (int bq = 0; bq < 8; bq += 2) BFLYW(x[g * 8 + bq], x[g * 8 + bq + 1], w);
        }
    }
    {   // stage 10
        u32 base = 0; if constexpr (P2) base = p2base(k1, 10);
        #pragma unroll
        for (int g = 0; g < 2; ++g)
            #pragma unroll
            for (int k = 0; k < 2; ++k) {
                u32 w = wC[2 + 2 * g + k]; if constexpr (P2) w = mmul(w, base);
                #pragma unroll
                for (int bq = 0; bq < 8; bq += 4) BFLYW(x[g * 8 + bq + k], x[g * 8 + bq + k + 2], w);
            }
    }
    {   // stage 11
        u32 base = 0; if constexpr (P2) base = p2base(k1, 11);
        #pragma unroll
        for (int g = 0; g < 2; ++g)
            #pragma unroll
            for (int k = 0; k < 4; ++k) {
                u32 w = wC[6 + 4 * g + k]; if constexpr (P2) w = mmul(w, base);
                BFLYW(x[g * 8 + k], x[g * 8 + k + 4], w);
            }
    }
    #pragma unroll
    for (int g = 0; g < 2; ++g)
        #pragma unroll
        for (int e = 0; e < 8; ++e) col[swz(u | ((u32)g << 7) | ((u32)e << 8))] = x[g * 8 + e];
}

// ---------------- pass 1: reference stages 1..11 per column -> g_mid -----------
__global__ void __launch_bounds__(1024, 1)
k_pass1(const void* __restrict__ in,
        const void* c0, const void* c1, const void* c2,
        const void* tw0, const void* tw1) {
    extern __shared__ u32 sh[];
    const void* ccand[3] = { c0, c1, c2 };
    bool fm_cos, fm_in;
    const void* coset = ccand[pick(ccand, 3, 3u, fm_cos)];   // coset_powers[1] == 3
    {   const void* tcand[2] = { tw0, tw1 };
        pick(tcand, 2, OMEGA, fm_in);                         // input shares canonical dtype
    }

    const u32 t  = threadIdx.x;
    const u32 b  = blockIdx.y;
    const u32 cb = blockIdx.x * 8u;
    const u32 r  = t >> 3, cc = t & 7u;
    const u32 base_in = b << 22;

    #pragma unroll
    for (int e = 0; e < 16; ++e) {
        u32 j1   = r + 128u * (u32)e;
        u32 gidx = j1 * 2048u + cb + cc;
        u32 v = ldval(in, base_in + gidx, fm_in);
        v = wmul(v, ldval(coset, gidx, fm_cos));   // wrapped `input * coset % P`
        sh[cc * SSTRIDE + swz(j1)] = v;
    }
    __syncthreads();

    ntt2048_team<false>(sh + (t >> 7) * SSTRIDE, t & 127u, 0u, (t >> 7) + 1u);
    __syncthreads();

    const u32 j2 = cb + cc;
    #pragma unroll
    for (int e = 0; e < 16; ++e) {
        u32 k1 = r + 128u * (u32)e;
        g_mid[base_in | (k1 * 2048u + j2)] = sh[cc * SSTRIDE + swz(k1)];
    }
}

// ---------------- pass 2: reference stages 12..22 per k1 -> d_out (float32) ----
__global__ void __launch_bounds__(1024, 1)
k_pass2(float* __restrict__ out) {
    extern __shared__ u32 sh[];
    const u32 t  = threadIdx.x;
    const u32 b  = blockIdx.y;
    const u32 rb = blockIdx.x * 8u;
    const u32 mbase = (b << 22) | (rb * 2048u);

    #pragma unroll
    for (int e = 0; e < 16; ++e) {
        u32 f = t + 1024u * (u32)e;
        u32 v = g_mid[mbase + f];
        sh[(f >> 11) * SSTRIDE + swz(f & 2047u)] = v;
    }
    __syncthreads();

    ntt2048_team<true>(sh + (t >> 7) * SSTRIDE, t & 127u, rb + (t >> 7), (t >> 7) + 1u);
    __syncthreads();

    const u32 r = t >> 3, cc = t & 7u;
    const u32 k1 = rb + cc;
    const u32 obase = b << 22;
    #pragma unroll
    for (int e = 0; e < 16; ++e) {
        u32 k2 = r + 128u * (u32)e;
        u32 v  = sh[cc * SSTRIDE + swz(k2)];
        out[obase + k1 + (k2 << 11)] = (float)v;   // output buffer is float32
    }
}

// ---------------- launch ----------------
extern "C" void kernel_launch(void* const* d_in, const int* in_sizes, int n_in,
                              void* d_out, int out_size) {
    const void* inp = nullptr;
    const void* tw[2] = { nullptr, nullptr };
    const void* cs[3] = { nullptr, nullptr, nullptr };
    int ntw = 0, ncs = 0;
    for (int i = 0; i < n_in; ++i) {
        long long sz = in_sizes[i];
        if (sz == (1LL << 25)) inp = d_in[i];
        else if (sz == (1LL << 21) && ntw < 2) tw[ntw++] = d_in[i];
        else if (sz == (1LL << 22) && ncs < 3) cs[ncs++] = d_in[i];
    }
    if (!inp)    inp   = d_in[0];
    if (ntw < 2) { tw[0] = d_in[1]; tw[1] = d_in[2]; }
    if (ncs < 3) { cs[0] = d_in[3]; cs[1] = d_in[4]; cs[2] = d_in[5]; }

    const int smem = 8 * SSTRIDE * (int)sizeof(u32);   // 69760 B
    cudaFuncSetAttribute(k_pass1, cudaFuncAttributeMaxDynamicSharedMemorySize, smem);
    cudaFuncSetAttribute(k_pass2, cudaFuncAttributeMaxDynamicSharedMemorySize, smem);

    k_setup<<<27, 256>>>(tw[0], tw[1]);
    dim3 grid(256, 8);
    k_pass1<<<grid, 1024, smem>>>(inp, cs[0], cs[1], cs[2], tw[0], tw[1]);
    k_pass2<<<grid, 1024, smem>>>((float*)d_out);
}

// round 9
// speedup vs baseline: 1.8968x; 1.2709x over previous
#include <cuda_runtime.h>
#include <cstdint>

typedef unsigned int u32;
typedef unsigned long long u64;

// ---------------- BabyBear constants (compile time) ----------------
constexpr u32 PRIME = 2013265921u;
constexpr u32 calc_pinv() {                 // -P^{-1} mod 2^32 (Montgomery, twiddle gen only)
    u32 inv = 1u;
    for (int i = 0; i < 5; ++i) inv *= (2u - PRIME * inv);
    return (u32)(0u - inv);
}
constexpr u32 PINV = calc_pinv();
constexpr u64 R1v  = (((u64)1) << 32) % PRIME;
constexpr u32 R2C  = (u32)((R1v * R1v) % PRIME);
constexpr u64 cpow(u64 b, u64 e) {
    u64 r = 1; b %= PRIME;
    while (e) { if (e & 1) r = r * b % PRIME; b = b * b % PRIME; e >>= 1; }
    return r;
}
constexpr u32 OMEGA = (u32)cpow(31, 480);                // GEN^((P-1)/2^22)
constexpr u32 WRAPC = (u32)((((u64)1) << 32) % PRIME);   // 2^32 - 2P = 268435454
constexpr u32 SSTRIDE = 2180u;                           // per-team shared stride (words)

// ---------------- device scratch ----------------
__device__ u32 g_mid[1u << 25];     // 128MB intermediate, standard-form residues
__device__ u32 g_twA_S[1024];       // standard:  omega_2048^q
__device__ u32 g_twA_M[1024];       // Montgomery: omega_2048^q * R
__device__ u32 g_twB_S[2048];       // standard:  omega^r
__device__ u32 g_seqS[29 * 128];    // slot-sequenced per-thread twiddles (standard)
__device__ u32 g_seqM[29 * 128];    // same, Montgomery form (for pass-2 twisting)

// ---------------- exact modular helpers (twiddle generation only) --------------
__device__ __forceinline__ u32 mmul(u32 a, u32 b) {      // a*b*R^{-1} mod P (exact)
    u64 t = (u64)a * b;
    u32 m = (u32)t * PINV;
    u32 r = (u32)((t + (u64)m * PRIME) >> 32);
    return r >= PRIME ? r - PRIME : r;
}

// ---------------- int32-wrap emulation, minimal-instruction forms --------------
// result = ((int32)(a*b)) mod P (floor-mod). Derivation:
//   m<2^31: r=m (needs <=1 sub since 2^31<2P). m>=2^31: (m-2^32) mod P = m-WRAPC in [2P-2^31,2P).
__device__ __forceinline__ u32 wmul(u32 a, u32 b) {
    u32 m = a * b;                        // low 32 bits, wraps like the reference
    u32 r = m - (m >> 31) * WRAPC;        // sign fixup, r < 2P
    return min(r, r - PRIME);             // conditional subtract via unsigned-min
}
// result = ((int32)(a+b)) mod P for a,b in [0,P): t<2P, same fixup
__device__ __forceinline__ u32 wadd(u32 a, u32 b) {
    u32 t = a + b;
    u32 r = t - (t >> 31) * WRAPC;
    return min(r, r - PRIME);
}
// (a-b) mod P for a,b in [0,P): wrap-free in the reference (|a-b|<P<2^31)
__device__ __forceinline__ u32 subm(u32 a, u32 b) {
    u32 r = a - b;
    return min(r, r + PRIME);             // if a<b, wrapped r is huge, r+P is the answer
}
__device__ __forceinline__ u32 swz(u32 j) { return j + (j >> 4); }

__device__ __forceinline__ u32 ldval(const void* p, u32 i, bool fm) {
    if (fm) return (u32)__ldg((const float*)p + i);
    return (u32)__ldg((const int*)p + i);
}
__device__ __forceinline__ int pick(const void* const* cand, int n, u32 want, bool& fm) {
    u32 fwant = __float_as_uint((float)want);
    for (int i = 0; i < n; ++i) {
        u32 raw = ((const u32*)cand[i])[1];
        if (raw == want)  { fm = false; return i; }
        if (raw == fwant) { fm = true;  return i; }
    }
    fm = false; return 0;
}

#define BFLYW(A, B, W) { u32 _vw = wmul((B), (W)); u32 _a = (A); (B) = subm(_a, _vw); (A) = wadd(_a, _vw); }
#define TBAR(id) asm volatile("bar.sync %0, 128;" :: "r"(id) : "memory")

// pass-2 per-stage base twiddle: omega^{k1 * 2^{11-s}} (exact standard form)
__device__ __forceinline__ u32 p2base(u32 k1, int s) {
    u32 E = k1 << (11 - s);               // < 2^21
    return mmul(__ldg(&g_twA_M[E >> 11]), __ldg(&g_twB_S[E & 2047u]));
}

// slot -> omega_2048 exponent for thread position u (matches consumption order below)
__device__ u32 slot_idx(u32 slot, u32 u) {
    u32 plow = u & 15u;
    if (slot == 0)  return plow << 6;                                   // s5
    if (slot < 3)   return (plow | ((slot - 1) << 4)) << 5;             // s6
    if (slot < 7)   return (plow | ((slot - 3) << 4)) << 4;             // s7
    if (slot < 15)  return (plow | ((slot - 7) << 4)) << 3;             // s8
    if (slot < 17)  return (u | ((slot - 15) << 7)) << 2;               // s9
    if (slot < 21)  { u32 g = (slot - 17) >> 1, k = (slot - 17) & 1;
                      return ((u | (g << 7)) | (k << 8)) << 1; }        // s10
    { u32 g = (slot - 21) >> 2, k = (slot - 21) & 3;
      return (u | (g << 7)) | (k << 8); }                               // s11
}

// ---------------- setup: all twiddle tables from the forward input table -------
__global__ void k_setup(const void* tw0, const void* tw1) {
    const void* cand[2] = { tw0, tw1 };
    bool fm;
    const void* tw = cand[pick(cand, 2, OMEGA, fm)];   // forward twiddles: tw[1] == omega
    u32 i = blockIdx.x * blockDim.x + threadIdx.x;
    if (i < 2048) {
        g_twB_S[i] = ldval(tw, i, fm);
    } else if (i < 3072) {
        u32 q = i - 2048;
        u32 v = ldval(tw, q << 11, fm);                // omega_2048^q exact
        g_twA_S[q] = v;
        g_twA_M[q] = mmul(v, R2C);
    } else if (i < 3072 + 29 * 128) {
        u32 s = i - 3072;
        u32 idx = slot_idx(s >> 7, s & 127u);
        u32 v = ldval(tw, idx << 11, fm);
        g_seqS[s] = v;
        g_seqM[s] = mmul(v, R2C);
    }
}

// per-thread coalesced slot twiddle, pass-selected table
template<bool P2>
__device__ __forceinline__ u32 seqw(int slot, u32 u) {
    return P2 ? __ldg(&g_seqM[slot * 128 + u]) : __ldg(&g_seqS[slot * 128 + u]);
}

// ---------------- 2048-point stage block (reference stages, wrapped ops) -------
// P2=false: reference stages 1..11. P2=true: stages 12..22 for fixed k1 (twisted).
// Caller must __syncthreads() before (data ready) and after (before cross-team reads).
template<bool P2>
__device__ __forceinline__ void ntt2048_team(u32* col, u32 u, u32 k1, u32 bar) {
    u32 x[16];
    u32 r7 = __brev(u) >> 25;                          // rev7(u)

    // ---- phase A (stages 1..4): j = 16u+e ; bitrev source = rev4(e)<<7 | rev7(u)
    #pragma unroll
    for (int e = 0; e < 16; ++e) {
        u32 rev4e = ((e & 1) << 3) | ((e & 2) << 1) | ((e & 4) >> 1) | ((e & 8) >> 3);
        x[e] = col[swz((rev4e << 7) | r7)];
    }
    if constexpr (P2) {
        u32 w = p2base(k1, 1);
        #pragma unroll
        for (int e = 0; e < 16; e += 2) BFLYW(x[e], x[e + 1], w);
    } else {
        #pragma unroll
        for (int e = 0; e < 16; e += 2) {               // w = 1, wrap-exact shortcut
            u32 a = x[e], v = x[e + 1];
            x[e] = wadd(a, v); x[e + 1] = subm(a, v);
        }
    }
    #pragma unroll
    for (int s = 2; s <= 4; ++s) {
        const int h = 1 << (s - 1);
        u32 base = 0;
        if constexpr (P2) base = p2base(k1, s);
        #pragma unroll
        for (int k = 0; k < h; ++k) {                   // k outer: one w per distinct twiddle
            u32 w;
            if constexpr (P2) w = mmul(__ldg(&g_twA_M[(u32)k << (11 - s)]), base);
            else              w = __ldg(&g_twA_S[(u32)k << (11 - s)]);
            #pragma unroll
            for (int bq = 0; bq < 16; bq += 2 * h)
                BFLYW(x[bq + k], x[bq + k + h], w);
        }
    }
    TBAR(bar);
    #pragma unroll
    for (int e = 0; e < 16; ++e) col[swz(16u * u + e)] = x[e];
    TBAR(bar);

    // ---- phase B (stages 5..8): j = (u&15) | ((u>>4)<<8) | (e<<4)
    u32 baseB = (u & 15u) | ((u >> 4) << 8);
    #pragma unroll
    for (int e = 0; e < 16; ++e) x[e] = col[swz(baseB | ((u32)e << 4))];
    {   // stage 5
        u32 w = seqw<P2>(0, u);
        if constexpr (P2) w = mmul(w, p2base(k1, 5));
        #pragma unroll
        for (int bq = 0; bq < 16; bq += 2) BFLYW(x[bq], x[bq + 1], w);
    }
    {   // stage 6
        u32 base = 0; if constexpr (P2) base = p2base(k1, 6);
        #pragma unroll
        for (int k = 0; k < 2; ++k) {
            u32 w = seqw<P2>(1 + k, u); if constexpr (P2) w = mmul(w, base);
            #pragma unroll
            for (int bq = 0; bq < 16; bq += 4) BFLYW(x[bq + k], x[bq + k + 2], w);
        }
    }
    {   // stage 7
        u32 base = 0; if constexpr (P2) base = p2base(k1, 7);
        #pragma unroll
        for (int k = 0; k < 4; ++k) {
            u32 w = seqw<P2>(3 + k, u); if constexpr (P2) w = mmul(w, base);
            #pragma unroll
            for (int bq = 0; bq < 16; bq += 8) BFLYW(x[bq + k], x[bq + k + 4], w);
        }
    }
    {   // stage 8
        u32 base = 0; if constexpr (P2) base = p2base(k1, 8);
        #pragma unroll
        for (int k = 0; k < 8; ++k) {
            u32 w = seqw<P2>(7 + k, u); if constexpr (P2) w = mmul(w, base);
            BFLYW(x[k], x[k + 8], w);
        }
    }
    #pragma unroll
    for (int e = 0; e < 16; ++e) col[swz(baseB | ((u32)e << 4))] = x[e];
    TBAR(bar);

    // ---- phase C (stages 9..11): j = u | (g<<7) | (e<<8)
    #pragma unroll
    for (int g = 0; g < 2; ++g)
        #pragma unroll
        for (int e = 0; e < 8; ++e) x[g * 8 + e] = col[swz(u | ((u32)g << 7) | ((u32)e << 8))];
    {   // stage 9
        u32 base = 0; if constexpr (P2) base = p2base(k1, 9);
        #pragma unroll
        for (int g = 0; g < 2; ++g) {
            u32 w = seqw<P2>(15 + g, u); if constexpr (P2) w = mmul(w, base);
            #pragma unroll
            for (int bq = 0; bq < 8; bq += 2) BFLYW(x[g * 8 + bq], x[g * 8 + bq + 1], w);
        }
    }
    {   // stage 10
        u32 base = 0; if constexpr (P2) base = p2base(k1, 10);
        #pragma unroll
        for (int g = 0; g < 2; ++g)
            #pragma unroll
            for (int k = 0; k < 2; ++k) {
                u32 w = seqw<P2>(17 + 2 * g + k, u); if constexpr (P2) w = mmul(w, base);
                #pragma unroll
                for (int bq = 0; bq < 8; bq += 4) BFLYW(x[g * 8 + bq + k], x[g * 8 + bq + k + 2], w);
            }
    }
    {   // stage 11
        u32 base = 0; if constexpr (P2) base = p2base(k1, 11);
        #pragma unroll
        for (int g = 0; g < 2; ++g)
            #pragma unroll
            for (int k = 0; k < 4; ++k) {
                u32 w = seqw<P2>(21 + 4 * g + k, u); if constexpr (P2) w = mmul(w, base);
                BFLYW(x[g * 8 + k], x[g * 8 + k + 4], w);
            }
    }
    #pragma unroll
    for (int g = 0; g < 2; ++g)
        #pragma unroll
        for (int e = 0; e < 8; ++e) col[swz(u | ((u32)g << 7) | ((u32)e << 8))] = x[g * 8 + e];
}

// ---------------- pass 1: reference stages 1..11 per column -> g_mid -----------
__global__ void __launch_bounds__(1024, 1)
k_pass1(const void* __restrict__ in,
        const void* c0, const void* c1, const void* c2,
        const void* tw0, const void* tw1) {
    extern __shared__ u32 sh[];
    const void* ccand[3] = { c0, c1, c2 };
    bool fm_cos, fm_in;
    const void* coset = ccand[pick(ccand, 3, 3u, fm_cos)];   // coset_powers[1] == 3
    {   const void* tcand[2] = { tw0, tw1 };
        pick(tcand, 2, OMEGA, fm_in);                         // input shares canonical dtype
    }

    const u32 t  = threadIdx.x;
    const u32 b  = blockIdx.y;
    const u32 cb = blockIdx.x * 8u;
    const u32 r  = t >> 3, cc = t & 7u;
    const u32 base_in = b << 22;

    #pragma unroll
    for (int e = 0; e < 16; ++e) {
        u32 j1   = r + 128u * (u32)e;
        u32 gidx = j1 * 2048u + cb + cc;
        u32 v = ldval(in, base_in + gidx, fm_in);
        v = wmul(v, ldval(coset, gidx, fm_cos));   // wrapped `input * coset % P`
        sh[cc * SSTRIDE + swz(j1)] = v;
    }
    __syncthreads();

    ntt2048_team<false>(sh + (t >> 7) * SSTRIDE, t & 127u, 0u, (t >> 7) + 1u);
    __syncthreads();

    const u32 j2 = cb + cc;
    #pragma unroll
    for (int e = 0; e < 16; ++e) {
        u32 k1 = r + 128u * (u32)e;
        g_mid[base_in | (k1 * 2048u + j2)] = sh[cc * SSTRIDE + swz(k1)];
    }
}

// ---------------- pass 2: reference stages 12..22 per k1 -> d_out (float32) ----
__global__ void __launch_bounds__(1024, 1)
k_pass2(float* __restrict__ out) {
    extern __shared__ u32 sh[];
    const u32 t  = threadIdx.x;
    const u32 b  = blockIdx.y;
    const u32 rb = blockIdx.x * 8u;
    const u32 mbase = (b << 22) | (rb * 2048u);

    #pragma unroll
    for (int e = 0; e < 16; ++e) {
        u32 f = t + 1024u * (u32)e;
        u32 v = g_mid[mbase + f];
        sh[(f >> 11) * SSTRIDE + swz(f & 2047u)] = v;
    }
    __syncthreads();

    ntt2048_team<true>(sh + (t >> 7) * SSTRIDE, t & 127u, rb + (t >> 7), (t >> 7) + 1u);
    __syncthreads();

    const u32 r = t >> 3, cc = t & 7u;
    const u32 k1 = rb + cc;
    const u32 obase = b << 22;
    #pragma unroll
    for (int e = 0; e < 16; ++e) {
        u32 k2 = r + 128u * (u32)e;
        u32 v  = sh[cc * SSTRIDE + swz(k2)];
        out[obase + k1 + (k2 << 11)] = (float)v;   // output buffer is float32
    }
}

// ---------------- launch ----------------
extern "C" void kernel_launch(void* const* d_in, const int* in_sizes, int n_in,
                              void* d_out, int out_size) {
    const void* inp = nullptr;
    const void* tw[2] = { nullptr, nullptr };
    const void* cs[3] = { nullptr, nullptr, nullptr };
    int ntw = 0, ncs = 0;
    for (int i = 0; i < n_in; ++i) {
        long long sz = in_sizes[i];
        if (sz == (1LL << 25)) inp = d_in[i];
        else if (sz == (1LL << 21) && ntw < 2) tw[ntw++] = d_in[i];
        else if (sz == (1LL << 22) && ncs < 3) cs[ncs++] = d_in[i];
    }
    if (!inp)    inp   = d_in[0];
    if (ntw < 2) { tw[0] = d_in[1]; tw[1] = d_in[2]; }
    if (ncs < 3) { cs[0] = d_in[3]; cs[1] = d_in[4]; cs[2] = d_in[5]; }

    const int smem = 8 * SSTRIDE * (int)sizeof(u32);   // 69760 B
    cudaFuncSetAttribute(k_pass1, cudaFuncAttributeMaxDynamicSharedMemorySize, smem);
    cudaFuncSetAttribute(k_pass2, cudaFuncAttributeMaxDynamicSharedMemorySize, smem);

    k_setup<<<27, 256>>>(tw[0], tw[1]);
    dim3 grid(256, 8);
    k_pass1<<<grid, 1024, smem>>>(inp, cs[0], cs[1], cs[2], tw[0], tw[1]);
    k_pass2<<<grid, 1024, smem>>>((float*)d_out);
}